// round 4
// baseline (speedup 1.0000x reference)
#include <cuda_runtime.h>
#include <cstdint>

// out[b,c,i,j] = x[b,c, i^3, j^3]   (H = W = 256)
// j^3 within an aligned float4 = lane reverse; i^3 = row shuffle.
// Persistent grid-stride kernel: one wave (148 SMs x 6 CTAs), each iteration
// moves 8 front-batched LDG.128 per thread (MLP=8), streaming cache hints.

static constexpr int W4      = 64;    // float4s per row
static constexpr int H       = 256;
static constexpr int UNROLL  = 8;
static constexpr int TPB     = 256;
static constexpr int CHUNK   = TPB * UNROLL;      // 2048 float4s per block-iter

__global__ void __launch_bounds__(TPB)
dualswitch_kernel(const float4* __restrict__ in, float4* __restrict__ out, int total4) {
    int stride = gridDim.x * CHUNK;
    for (int base0 = blockIdx.x * CHUNK; base0 < total4; base0 += stride) {
        int base = base0 + threadIdx.x;

        float4 v[UNROLL];
        #pragma unroll
        for (int u = 0; u < UNROLL; u++) {
            int idx  = base + u * TPB;
            int g    = idx & (W4 - 1);
            int rest = idx >> 6;
            int i    = rest & (H - 1);
            int bc   = rest >> 8;
            int in_idx = ((bc << 8) | (i ^ 3)) * W4 + g;
            v[u] = __ldcs(in + in_idx);
        }

        #pragma unroll
        for (int u = 0; u < UNROLL; u++) {
            int idx = base + u * TPB;
            __stcs(out + idx, make_float4(v[u].w, v[u].z, v[u].y, v[u].x));
        }
    }
}

extern "C" void kernel_launch(void* const* d_in, const int* in_sizes, int n_in,
                              void* d_out, int out_size) {
    const float4* in  = (const float4*)d_in[0];
    float4*       out = (float4*)d_out;
    int total4 = out_size / 4;                 // 25,165,824 (multiple of CHUNK)
    int blocks = 148 * 6;                      // one full wave at occ 6
    dualswitch_kernel<<<blocks, TPB>>>(in, out, total4);
}

// round 5
// speedup vs baseline: 1.1012x; 1.1012x over previous
#include <cuda_runtime.h>
#include <cstdint>

// out[b,c,i,j] = x[b,c, i^3, j^3]   (H = W = 256)
// j^3 within an aligned float4 = lane reverse; i^3 = row shuffle.
// Non-persistent launch (consecutive-blockIdx waves keep the concurrent TLB
// footprint small). 8 front-batched LDG.128 per thread (MLP=8), streaming
// cache hints. TPB=512 halves CTA count at identical occupancy.

static constexpr int W4     = 64;    // float4s per row
static constexpr int H      = 256;
static constexpr int UNROLL = 8;
static constexpr int TPB    = 512;

__global__ void __launch_bounds__(TPB)
dualswitch_kernel(const float4* __restrict__ in, float4* __restrict__ out) {
    int base = blockIdx.x * (TPB * UNROLL) + threadIdx.x;

    float4 v[UNROLL];
    #pragma unroll
    for (int u = 0; u < UNROLL; u++) {
        int idx  = base + u * TPB;
        int g    = idx & (W4 - 1);
        int rest = idx >> 6;
        int i    = rest & (H - 1);
        int bc   = rest >> 8;
        int in_idx = ((bc << 8) | (i ^ 3)) * W4 + g;
        v[u] = __ldcs(in + in_idx);
    }

    #pragma unroll
    for (int u = 0; u < UNROLL; u++) {
        int idx = base + u * TPB;
        __stcs(out + idx, make_float4(v[u].w, v[u].z, v[u].y, v[u].x));
    }
}

extern "C" void kernel_launch(void* const* d_in, const int* in_sizes, int n_in,
                              void* d_out, int out_size) {
    const float4* in  = (const float4*)d_in[0];
    float4*       out = (float4*)d_out;
    int total4 = out_size / 4;                 // 25,165,824
    int blocks = total4 / (TPB * UNROLL);      // exact: 6,144
    dualswitch_kernel<<<blocks, TPB>>>(in, out);
}